// round 4
// baseline (speedup 1.0000x reference)
#include <cuda_runtime.h>
#include <cstdint>

// ---------------------------------------------------------------------------
// TrajectoryFK fused: TMA row staging + single-pass decoupled-lookback affine
// scan + unrolled FK tree + TMA bulk output store.
//
// element e_t = (M_t, u_t), M_t = rotmat(joint1 6d), u_t = M_t @ vel_t
// combine(a earlier, b later) = (a.M @ b.M, a.u + a.M @ b.u)
// ---------------------------------------------------------------------------

constexpr int L    = 65536;
constexpr int TPB  = 128;        // threads = timesteps per block
constexpr int NB   = L / TPB;    // 512 blocks
constexpr int ROWF = 132;        // floats per timestep row

// shared memory layout (float indices)
constexpr int S_ROW  = 0;                     // 128*132 staged input rows
constexpr int S_OUT  = TPB * ROWF;            // 16896: 128*66 output tile
constexpr int S_WAGG = S_OUT + TPB * 66;      // 25344: 4 warp aggs * 12
constexpr int S_PREF = S_WAGG + 48;           // 25392: block exclusive prefix
constexpr int S_OFF  = S_PREF + 12;           // 25404: 66 offset floats
constexpr int S_MBAR = S_OFF + 66;            // 25470 (even -> 8B aligned)
constexpr int SMEM_BYTES = (S_MBAR + 4) * 4;  // 101,896 B

// lookback state
__device__ float4   g_aggp[NB][3];   // block aggregate payload
__device__ float4   g_incp[NB][3];   // block inclusive payload
__device__ unsigned g_flag[NB];      // 0=invalid 1=aggregate 2=inclusive

// ---------------------------------------------------------------------------
__device__ __forceinline__ void d6_to_mat(const float* d, float* m) {
    float a1x = d[0], a1y = d[1], a1z = d[2];
    float a2x = d[3], a2y = d[4], a2z = d[5];
    float n1 = a1x * a1x + a1y * a1y + a1z * a1z;
    float i1 = rsqrtf(fmaxf(n1, 1e-24f));
    float b1x = a1x * i1, b1y = a1y * i1, b1z = a1z * i1;
    float dp = b1x * a2x + b1y * a2y + b1z * a2z;
    float c2x = a2x - b1x * dp, c2y = a2y - b1y * dp, c2z = a2z - b1z * dp;
    float n2 = c2x * c2x + c2y * c2y + c2z * c2z;
    float i2 = rsqrtf(fmaxf(n2, 1e-24f));
    float b2x = c2x * i2, b2y = c2y * i2, b2z = c2z * i2;
    float b3x = b1y * b2z - b1z * b2y;
    float b3y = b1z * b2x - b1x * b2z;
    float b3z = b1x * b2y - b1y * b2x;
    m[0] = b1x; m[1] = b2x; m[2] = b3x;
    m[3] = b1y; m[4] = b2y; m[5] = b3y;
    m[6] = b1z; m[7] = b2z; m[8] = b3z;
}

__device__ __forceinline__ void mat3mul(float* __restrict__ c,
                                        const float* a, const float* b) {
#pragma unroll
    for (int r = 0; r < 3; r++) {
        float a0 = a[r * 3], a1 = a[r * 3 + 1], a2 = a[r * 3 + 2];
#pragma unroll
        for (int k = 0; k < 3; k++)
            c[r * 3 + k] = a0 * b[k] + a1 * b[3 + k] + a2 * b[6 + k];
    }
}

// r = a ∘ b (a earlier); alias-safe
__device__ __forceinline__ void aff_combine(float* r, const float* a, const float* b) {
    float t[12];
#pragma unroll
    for (int rr = 0; rr < 3; rr++) {
        float a0 = a[rr * 3], a1 = a[rr * 3 + 1], a2 = a[rr * 3 + 2];
#pragma unroll
        for (int k = 0; k < 3; k++)
            t[rr * 3 + k] = a0 * b[k] + a1 * b[3 + k] + a2 * b[6 + k];
        t[9 + rr] = a[9 + rr] + a0 * b[9] + a1 * b[10] + a2 * b[11];
    }
#pragma unroll
    for (int i = 0; i < 12; i++) r[i] = t[i];
}

__device__ __forceinline__ void aff_identity(float* v) {
#pragma unroll
    for (int i = 0; i < 12; i++) v[i] = 0.0f;
    v[0] = v[4] = v[8] = 1.0f;
}

// ---- memory-order helpers -------------------------------------------------
__device__ __forceinline__ void flag_release(unsigned* p, unsigned v) {
    asm volatile("st.release.gpu.u32 [%0], %1;" :: "l"(p), "r"(v) : "memory");
}
__device__ __forceinline__ unsigned flag_acquire(const unsigned* p) {
    unsigned v;
    asm volatile("ld.acquire.gpu.u32 %0, [%1];" : "=r"(v) : "l"(p) : "memory");
    return v;
}

__device__ __forceinline__ void pay_store(float4* dst, const float* v) {
    dst[0] = make_float4(v[0], v[1], v[2], v[3]);
    dst[1] = make_float4(v[4], v[5], v[6], v[7]);
    dst[2] = make_float4(v[8], v[9], v[10], v[11]);
}
__device__ __forceinline__ void pay_load(const float4* src, float* v) {
    float4 a = src[0], b = src[1], c = src[2];
    v[0] = a.x; v[1] = a.y; v[2]  = a.z; v[3]  = a.w;
    v[4] = b.x; v[5] = b.y; v[6]  = b.z; v[7]  = b.w;
    v[8] = c.x; v[9] = c.y; v[10] = c.z; v[11] = c.w;
}

// ---- FK helpers -----------------------------------------------------------
__device__ __forceinline__ void fk_rot(float* Rc, const float* Rp,
                                       const float* r, int j) {
    float d6[6];
#pragma unroll
    for (int i = 0; i < 6; i++) d6[i] = r[6 * j + i];
    float M[9];
    d6_to_mat(d6, M);
    mat3mul(Rc, Rp, M);
}

__device__ __forceinline__ void fk_pos(float* pc, const float* pp, const float* Rp,
                                       const float* s_off, int j) {
    float ox = s_off[j * 3], oy = s_off[j * 3 + 1], oz = s_off[j * 3 + 2];
    pc[0] = pp[0] + Rp[0] * ox + Rp[1] * oy + Rp[2] * oz;
    pc[1] = pp[1] + Rp[3] * ox + Rp[4] * oy + Rp[5] * oz;
    pc[2] = pp[2] + Rp[6] * ox + Rp[7] * oy + Rp[8] * oz;
}

// ---------------------------------------------------------------------------
__global__ void fk_init() {
    int i = blockIdx.x * blockDim.x + threadIdx.x;
    if (i < NB) g_flag[i] = 0;
}

// ---------------------------------------------------------------------------
extern "C" __global__ void __launch_bounds__(TPB)
fk_fused(const float* __restrict__ pred, const float* __restrict__ offs,
         float* __restrict__ out) {
    extern __shared__ float smem[];
    float* s_row  = smem + S_ROW;
    float* s_out  = smem + S_OUT;
    float* s_wagg = smem + S_WAGG;
    float* s_pref = smem + S_PREF;
    float* s_off  = smem + S_OFF;

    const int tid  = threadIdx.x;
    const int lane = tid & 31;
    const int warp = tid >> 5;
    const int b    = blockIdx.x;
    const size_t base = (size_t)b * TPB;

    uint32_t mbar = (uint32_t)__cvta_generic_to_shared(smem + S_MBAR);
    uint32_t srow = (uint32_t)__cvta_generic_to_shared(s_row);

    // ---- issue TMA bulk load of this block's 128 rows ----------------------
    if (tid == 0) {
        asm volatile("mbarrier.init.shared.b64 [%0], 1;" :: "r"(mbar) : "memory");
        asm volatile("mbarrier.arrive.expect_tx.shared.b64 _, [%0], %1;"
                     :: "r"(mbar), "r"((unsigned)(TPB * ROWF * 4)) : "memory");
        asm volatile(
            "cp.async.bulk.shared::cluster.global.mbarrier::complete_tx::bytes "
            "[%0], [%1], %2, [%3];"
            :: "r"(srow), "l"(pred + base * ROWF),
               "r"((unsigned)(TPB * ROWF * 4)), "r"(mbar) : "memory");
    }
    if (tid < 66) s_off[tid] = offs[tid];

    // ---- build affine element straight from gmem (overlaps TMA) ------------
    const float* grow = pred + (base + tid) * ROWF;
    float2 v01 = *(const float2*)(grow);
    float  vz  = grow[2];
    float2 e0 = *(const float2*)(grow + 6);
    float2 e1 = *(const float2*)(grow + 8);
    float2 e2 = *(const float2*)(grow + 10);
    float d6[6] = {e0.x, e0.y, e1.x, e1.y, e2.x, e2.y};

    float val[12];
    d6_to_mat(d6, val);
    float vx = v01.x, vy = v01.y;
    val[9]  = val[0] * vx + val[1] * vy + val[2] * vz;
    val[10] = val[3] * vx + val[4] * vy + val[5] * vz;
    val[11] = val[6] * vx + val[7] * vy + val[8] * vz;

    // ---- warp inclusive scan ----------------------------------------------
#pragma unroll
    for (int off = 1; off < 32; off <<= 1) {
        float o[12];
#pragma unroll
        for (int i = 0; i < 12; i++)
            o[i] = __shfl_up_sync(0xffffffffu, val[i], off);
        if (lane >= off) aff_combine(val, o, val);
    }
    if (lane == 31) {
#pragma unroll
        for (int i = 0; i < 12; i++) s_wagg[warp * 12 + i] = val[i];
    }
    __syncthreads();

    // ---- warp 0: publish aggregate, decoupled lookback ---------------------
    if (warp == 0) {
        float agg[12];
        if (lane == 0) {
#pragma unroll
            for (int i = 0; i < 12; i++) agg[i] = s_wagg[i];
            aff_combine(agg, agg, s_wagg + 12);
            aff_combine(agg, agg, s_wagg + 24);
            aff_combine(agg, agg, s_wagg + 36);
            if (b == 0) {
                pay_store(g_incp[0], agg);
                flag_release(&g_flag[0], 2u);
                aff_identity(s_pref);
            } else {
                pay_store(g_aggp[b], agg);
                flag_release(&g_flag[b], 1u);
            }
        }
        if (b > 0) {
            float acc[12];
            aff_identity(acc);
            int wend = b;
            for (;;) {
                int p = wend - 32 + lane;
                float v[12];
                unsigned f;
                if (p >= 0) {
                    do { f = flag_acquire(&g_flag[p]); } while (f == 0);
                    pay_load((f == 2u) ? g_incp[p] : g_aggp[p], v);
                } else {
                    f = 2u;
                    aff_identity(v);
                }
                unsigned m2 = __ballot_sync(0xffffffffu, f == 2u);
                if (m2) {
                    int h = 31 - __clz(m2);   // latest inclusive in window
                    if (lane < h) aff_identity(v);
                }
                // ordered reduce (ascending block id) -> lane 0
#pragma unroll
                for (int off = 1; off < 32; off <<= 1) {
                    float o[12];
#pragma unroll
                    for (int i = 0; i < 12; i++)
                        o[i] = __shfl_down_sync(0xffffffffu, v[i], off);
                    if (((lane & (2 * off - 1)) == 0) && lane + off < 32)
                        aff_combine(v, v, o);
                }
                if (lane == 0) aff_combine(acc, v, acc);
                if (m2) break;
                wend -= 32;
            }
            if (lane == 0) {
#pragma unroll
                for (int i = 0; i < 12; i++) s_pref[i] = acc[i];
                float inc[12];
                aff_combine(inc, acc, agg);
                pay_store(g_incp[b], inc);
                flag_release(&g_flag[b], 2u);
            }
        }
    }

    // ---- all threads: block-local inclusive --------------------------------
    float pre[12];
    aff_identity(pre);
    for (int w = 0; w < warp; w++) aff_combine(pre, pre, s_wagg + w * 12);
    float linc[12];
    aff_combine(linc, pre, val);

    __syncthreads();          // s_pref ready

    float G[12];
    aff_combine(G, s_pref, linc);

    // ---- wait for TMA row staging ------------------------------------------
    {
        unsigned done;
        asm volatile(
            "{\n\t.reg .pred p;\n\t"
            "mbarrier.try_wait.parity.acquire.cta.shared::cta.b64 p, [%1], 0;\n\t"
            "selp.b32 %0, 1, 0, p;\n\t}"
            : "=r"(done) : "r"(mbar) : "memory");
        while (!done) {
            asm volatile(
                "{\n\t.reg .pred p;\n\t"
                "mbarrier.try_wait.parity.acquire.cta.shared::cta.b64 p, [%1], 0, 0x989680;\n\t"
                "selp.b32 %0, 1, 0, p;\n\t}"
                : "=r"(done) : "r"(mbar) : "memory");
        }
    }

    // ---- FK tree (reads from smem rows, emits to smem output tile) ---------
    const float* r = s_row + tid * ROWF;
    float* o = s_out + tid * 66;
#define EMIT(j, p) { o[3*(j)] = (p)[0]; o[3*(j)+1] = (p)[1]; o[3*(j)+2] = (p)[2]; }

    const float* R = G;
    float pos0[3] = {G[9], G[10], G[11]};
    EMIT(0, pos0);
    float pos1[3]; fk_pos(pos1, pos0, R, s_off, 1);  EMIT(1, pos1);

    // chain 1 -> 4 -> 7 -> 10
    float R4[9];  fk_rot(R4, R, r, 4);
    float pos4[3];  fk_pos(pos4, pos1, R, s_off, 4);   EMIT(4, pos4);
    float R7[9];  fk_rot(R7, R4, r, 7);
    float pos7[3];  fk_pos(pos7, pos4, R4, s_off, 7);  EMIT(7, pos7);
    float pos10[3]; fk_pos(pos10, pos7, R7, s_off, 10); EMIT(10, pos10);

    // chain 0 -> 2 -> 5 -> 8 -> 11
    float R2[9];  fk_rot(R2, R, r, 2);
    float pos2[3];  fk_pos(pos2, pos0, R, s_off, 2);   EMIT(2, pos2);
    float R5[9];  fk_rot(R5, R2, r, 5);
    float pos5[3];  fk_pos(pos5, pos2, R2, s_off, 5);  EMIT(5, pos5);
    float R8[9];  fk_rot(R8, R5, r, 8);
    float pos8[3];  fk_pos(pos8, pos5, R5, s_off, 8);  EMIT(8, pos8);
    float pos11[3]; fk_pos(pos11, pos8, R8, s_off, 11); EMIT(11, pos11);

    // chain 0 -> 3 -> 6 -> 9
    float R3[9];  fk_rot(R3, R, r, 3);
    float pos3[3];  fk_pos(pos3, pos0, R, s_off, 3);   EMIT(3, pos3);
    float R6[9];  fk_rot(R6, R3, r, 6);
    float pos6[3];  fk_pos(pos6, pos3, R3, s_off, 6);  EMIT(6, pos6);
    float R9[9];  fk_rot(R9, R6, r, 9);
    float pos9[3];  fk_pos(pos9, pos6, R6, s_off, 9);  EMIT(9, pos9);

    // 9 -> 12 -> 15
    float R12[9]; fk_rot(R12, R9, r, 12);
    float pos12[3]; fk_pos(pos12, pos9, R9, s_off, 12); EMIT(12, pos12);
    float pos15[3]; fk_pos(pos15, pos12, R12, s_off, 15); EMIT(15, pos15);

    // 9 -> 13 -> 16 -> 18 -> 20
    float R13[9]; fk_rot(R13, R9, r, 13);
    float pos13[3]; fk_pos(pos13, pos9, R9, s_off, 13); EMIT(13, pos13);
    float R16[9]; fk_rot(R16, R13, r, 16);
    float pos16[3]; fk_pos(pos16, pos13, R13, s_off, 16); EMIT(16, pos16);
    float R18[9]; fk_rot(R18, R16, r, 18);
    float pos18[3]; fk_pos(pos18, pos16, R16, s_off, 18); EMIT(18, pos18);
    float pos20[3]; fk_pos(pos20, pos18, R18, s_off, 20); EMIT(20, pos20);

    // 9 -> 14 -> 17 -> 19 -> 21
    float R14[9]; fk_rot(R14, R9, r, 14);
    float pos14[3]; fk_pos(pos14, pos9, R9, s_off, 14); EMIT(14, pos14);
    float R17[9]; fk_rot(R17, R14, r, 17);
    float pos17[3]; fk_pos(pos17, pos14, R14, s_off, 17); EMIT(17, pos17);
    float R19[9]; fk_rot(R19, R17, r, 19);
    float pos19[3]; fk_pos(pos19, pos17, R17, s_off, 19); EMIT(19, pos19);
    float pos21[3]; fk_pos(pos21, pos19, R19, s_off, 21); EMIT(21, pos21);
#undef EMIT

    __syncthreads();

    // ---- bulk store of the 128x66 output tile ------------------------------
    if (tid == 0) {
        uint32_t sout = (uint32_t)__cvta_generic_to_shared(s_out);
        asm volatile("fence.proxy.async.shared::cta;" ::: "memory");
        asm volatile(
            "cp.async.bulk.global.shared::cta.bulk_group [%0], [%1], %2;"
            :: "l"(out + base * 66), "r"(sout),
               "r"((unsigned)(TPB * 66 * 4)) : "memory");
        asm volatile("cp.async.bulk.commit_group;" ::: "memory");
        asm volatile("cp.async.bulk.wait_group 0;" ::: "memory");
    }
    __syncthreads();
}

// ---------------------------------------------------------------------------
extern "C" void kernel_launch(void* const* d_in, const int* in_sizes, int n_in,
                              void* d_out, int out_size) {
    const float* pred = (const float*)d_in[0];   // (65536, 22, 6) f32
    const float* offs = (const float*)d_in[1];   // (22, 3) f32
    float* out = (float*)d_out;                  // (65536, 22, 3) f32

    cudaFuncSetAttribute(fk_fused, cudaFuncAttributeMaxDynamicSharedMemorySize,
                         SMEM_BYTES);
    fk_init<<<2, 256>>>();
    fk_fused<<<NB, TPB, SMEM_BYTES>>>(pred, offs, out);
}

// round 6
// speedup vs baseline: 1.2087x; 1.2087x over previous
#include <cuda_runtime.h>
#include <cstdint>

// ---------------------------------------------------------------------------
// TrajectoryFK, 3-kernel parallel pipeline:
//   A: per-128-block ordered affine reduce (via scan) -> g_agg
//   B: single-block scan of 512 aggregates -> g_pref (exclusive)
//   C: TMA row staging + in-block rescan + FK tree + TMA bulk store
//
// affine element e_t = (M_t, u_t): M_t = rotmat(joint1 6d), u_t = M_t @ vel_t
// combine(a earlier, b later) = (a.M @ b.M, a.u + a.M @ b.u)
// ---------------------------------------------------------------------------

constexpr int L    = 65536;
constexpr int TPB  = 128;        // timesteps per block (A and C)
constexpr int NB   = L / TPB;    // 512 blocks
constexpr int ROWF = 132;        // floats per timestep row (22*6)

// kernel C shared layout (float indices)
constexpr int S_ROW  = 0;                     // 128*132 staged rows
constexpr int S_OUT  = TPB * ROWF;            // 16896: 128*66 output tile
constexpr int S_WAGG = S_OUT + TPB * 66;      // 25344: 4 warp aggs * 12
constexpr int S_OFF  = S_WAGG + 48;           // 25392: 66 offsets
constexpr int S_MBAR = S_OFF + 66;            // 25458 (even -> 8B aligned)
constexpr int SMEM_C = (S_MBAR + 2) * 4;      // 101,840 B

__device__ float g_agg[NB * 12];    // block aggregates
__device__ float g_pref[NB * 12];   // exclusive block prefixes

// ---------------------------------------------------------------------------
__device__ __forceinline__ void d6_to_mat(const float* d, float* m) {
    float a1x = d[0], a1y = d[1], a1z = d[2];
    float a2x = d[3], a2y = d[4], a2z = d[5];
    float n1 = a1x * a1x + a1y * a1y + a1z * a1z;
    float i1 = rsqrtf(fmaxf(n1, 1e-24f));
    float b1x = a1x * i1, b1y = a1y * i1, b1z = a1z * i1;
    float dp = b1x * a2x + b1y * a2y + b1z * a2z;
    float c2x = a2x - b1x * dp, c2y = a2y - b1y * dp, c2z = a2z - b1z * dp;
    float n2 = c2x * c2x + c2y * c2y + c2z * c2z;
    float i2 = rsqrtf(fmaxf(n2, 1e-24f));
    float b2x = c2x * i2, b2y = c2y * i2, b2z = c2z * i2;
    float b3x = b1y * b2z - b1z * b2y;
    float b3y = b1z * b2x - b1x * b2z;
    float b3z = b1x * b2y - b1y * b2x;
    m[0] = b1x; m[1] = b2x; m[2] = b3x;
    m[3] = b1y; m[4] = b2y; m[5] = b3y;
    m[6] = b1z; m[7] = b2z; m[8] = b3z;
}

__device__ __forceinline__ void mat3mul(float* __restrict__ c,
                                        const float* a, const float* b) {
#pragma unroll
    for (int r = 0; r < 3; r++) {
        float a0 = a[r * 3], a1 = a[r * 3 + 1], a2 = a[r * 3 + 2];
#pragma unroll
        for (int k = 0; k < 3; k++)
            c[r * 3 + k] = a0 * b[k] + a1 * b[3 + k] + a2 * b[6 + k];
    }
}

// r = a ∘ b (a earlier); alias-safe
__device__ __forceinline__ void aff_combine(float* r, const float* a, const float* b) {
    float t[12];
#pragma unroll
    for (int rr = 0; rr < 3; rr++) {
        float a0 = a[rr * 3], a1 = a[rr * 3 + 1], a2 = a[rr * 3 + 2];
#pragma unroll
        for (int k = 0; k < 3; k++)
            t[rr * 3 + k] = a0 * b[k] + a1 * b[3 + k] + a2 * b[6 + k];
        t[9 + rr] = a[9 + rr] + a0 * b[9] + a1 * b[10] + a2 * b[11];
    }
#pragma unroll
    for (int i = 0; i < 12; i++) r[i] = t[i];
}

__device__ __forceinline__ void aff_identity(float* v) {
#pragma unroll
    for (int i = 0; i < 12; i++) v[i] = 0.0f;
    v[0] = v[4] = v[8] = 1.0f;
}

// build affine element for timestep row at gmem pointer
__device__ __forceinline__ void build_elem(const float* grow, float* val) {
    float2 v01 = *(const float2*)(grow);
    float  vz  = grow[2];
    float2 e0 = *(const float2*)(grow + 6);
    float2 e1 = *(const float2*)(grow + 8);
    float2 e2 = *(const float2*)(grow + 10);
    float d6[6] = {e0.x, e0.y, e1.x, e1.y, e2.x, e2.y};
    d6_to_mat(d6, val);
    float vx = v01.x, vy = v01.y;
    val[9]  = val[0] * vx + val[1] * vy + val[2] * vz;
    val[10] = val[3] * vx + val[4] * vy + val[5] * vz;
    val[11] = val[6] * vx + val[7] * vy + val[8] * vz;
}

// warp-ordered inclusive scan of affine elements (proven-correct path)
__device__ __forceinline__ void warp_incl_scan(float* val, int lane) {
#pragma unroll
    for (int off = 1; off < 32; off <<= 1) {
        float o[12];
#pragma unroll
        for (int i = 0; i < 12; i++)
            o[i] = __shfl_up_sync(0xffffffffu, val[i], off);
        if (lane >= off) aff_combine(val, o, val);
    }
}

// ---------------------------------------------------------------------------
// Kernel A: block aggregate via warp inclusive scans (lane31 = warp product).
// ---------------------------------------------------------------------------
__global__ void __launch_bounds__(TPB)
kernelA(const float* __restrict__ pred) {
    const int tid  = threadIdx.x;
    const int lane = tid & 31;
    const int warp = tid >> 5;
    const size_t t = (size_t)blockIdx.x * TPB + tid;

    float val[12];
    build_elem(pred + t * ROWF, val);
    warp_incl_scan(val, lane);

    __shared__ float s_wagg[4][12];
    if (lane == 31) {
#pragma unroll
        for (int i = 0; i < 12; i++) s_wagg[warp][i] = val[i];
    }
    __syncthreads();

    if (tid == 0) {
        float agg[12];
#pragma unroll
        for (int i = 0; i < 12; i++) agg[i] = s_wagg[0][i];
        aff_combine(agg, agg, s_wagg[1]);
        aff_combine(agg, agg, s_wagg[2]);
        aff_combine(agg, agg, s_wagg[3]);
#pragma unroll
        for (int i = 0; i < 12; i++) g_agg[blockIdx.x * 12 + i] = agg[i];
    }
}

// ---------------------------------------------------------------------------
// Kernel B: scan 512 block aggregates -> exclusive prefixes.
// ---------------------------------------------------------------------------
__global__ void __launch_bounds__(NB)
kernelB() {
    const int tid = threadIdx.x, lane = tid & 31, warp = tid >> 5;
    float val[12];
#pragma unroll
    for (int i = 0; i < 12; i++) val[i] = g_agg[tid * 12 + i];

    warp_incl_scan(val, lane);

    __shared__ float s_wagg[16][12];
    __shared__ float s_wpre[16][12];
    if (lane == 31) {
#pragma unroll
        for (int i = 0; i < 12; i++) s_wagg[warp][i] = val[i];
    }
    __syncthreads();

    // warp 0 scans the 16 warp aggregates -> exclusive warp prefixes
    if (warp == 0 && lane < 16) {
        float w[12];
#pragma unroll
        for (int i = 0; i < 12; i++) w[i] = s_wagg[lane][i];
#pragma unroll
        for (int off = 1; off < 16; off <<= 1) {
            float o[12];
#pragma unroll
            for (int i = 0; i < 12; i++)
                o[i] = __shfl_up_sync(0x0000ffffu, w[i], off);
            if (lane >= off) aff_combine(w, o, w);
        }
        float ex[12];
#pragma unroll
        for (int i = 0; i < 12; i++)
            ex[i] = __shfl_up_sync(0x0000ffffu, w[i], 1);
        if (lane == 0) aff_identity(ex);
#pragma unroll
        for (int i = 0; i < 12; i++) s_wpre[lane][i] = ex[i];
    }
    __syncthreads();

    float inc[12];
    aff_combine(inc, s_wpre[warp], val);

    if (tid == 0) {
        float id[12];
        aff_identity(id);
#pragma unroll
        for (int i = 0; i < 12; i++) g_pref[i] = id[i];
    }
    if (tid < NB - 1) {
#pragma unroll
        for (int i = 0; i < 12; i++) g_pref[(tid + 1) * 12 + i] = inc[i];
    }
}

// ---------------------------------------------------------------------------
// Kernel C: TMA row staging + in-block rescan + FK tree + TMA bulk store.
// ---------------------------------------------------------------------------
__device__ __forceinline__ void fk_rot(float* Rc, const float* Rp,
                                       const float* r, int j) {
    float d6[6];
#pragma unroll
    for (int i = 0; i < 6; i++) d6[i] = r[6 * j + i];
    float M[9];
    d6_to_mat(d6, M);
    mat3mul(Rc, Rp, M);
}

__device__ __forceinline__ void fk_pos(float* pc, const float* pp, const float* Rp,
                                       const float* s_off, int j) {
    float ox = s_off[j * 3], oy = s_off[j * 3 + 1], oz = s_off[j * 3 + 2];
    pc[0] = pp[0] + Rp[0] * ox + Rp[1] * oy + Rp[2] * oz;
    pc[1] = pp[1] + Rp[3] * ox + Rp[4] * oy + Rp[5] * oz;
    pc[2] = pp[2] + Rp[6] * ox + Rp[7] * oy + Rp[8] * oz;
}

extern "C" __global__ void __launch_bounds__(TPB)
kernelC(const float* __restrict__ pred, const float* __restrict__ offs,
        float* __restrict__ out) {
    extern __shared__ float smem[];
    float* s_row  = smem + S_ROW;
    float* s_out  = smem + S_OUT;
    float* s_wagg = smem + S_WAGG;
    float* s_off  = smem + S_OFF;

    const int tid  = threadIdx.x;
    const int lane = tid & 31;
    const int warp = tid >> 5;
    const int b    = blockIdx.x;
    const size_t base = (size_t)b * TPB;

    uint32_t mbar = (uint32_t)__cvta_generic_to_shared(smem + S_MBAR);
    uint32_t srow = (uint32_t)__cvta_generic_to_shared(s_row);

    // ---- issue TMA bulk load of this block's 128 rows ----------------------
    if (tid == 0) {
        asm volatile("mbarrier.init.shared.b64 [%0], 1;" :: "r"(mbar) : "memory");
        asm volatile("fence.proxy.async.shared::cta;" ::: "memory");
        asm volatile("mbarrier.arrive.expect_tx.shared.b64 _, [%0], %1;"
                     :: "r"(mbar), "r"((unsigned)(TPB * ROWF * 4)) : "memory");
        asm volatile(
            "cp.async.bulk.shared::cluster.global.mbarrier::complete_tx::bytes "
            "[%0], [%1], %2, [%3];"
            :: "r"(srow), "l"(pred + base * ROWF),
               "r"((unsigned)(TPB * ROWF * 4)), "r"(mbar) : "memory");
    }
    if (tid < 66) s_off[tid] = offs[tid];

    // ---- rebuild element from gmem (L2-hot sectors from kernel A) ----------
    float val[12];
    build_elem(pred + (base + tid) * ROWF, val);
    warp_incl_scan(val, lane);

    if (lane == 31) {
#pragma unroll
        for (int i = 0; i < 12; i++) s_wagg[warp * 12 + i] = val[i];
    }
    __syncthreads();

    // block-local inclusive, then global with block prefix
    float pre[12];
    aff_identity(pre);
    for (int w = 0; w < warp; w++) aff_combine(pre, pre, s_wagg + w * 12);
    float linc[12];
    aff_combine(linc, pre, val);

    float P[12];
#pragma unroll
    for (int i = 0; i < 12; i++) P[i] = __ldg(&g_pref[b * 12 + i]);
    float G[12];
    aff_combine(G, P, linc);

    // ---- wait for TMA row staging ------------------------------------------
    {
        unsigned done;
        asm volatile(
            "{\n\t.reg .pred p;\n\t"
            "mbarrier.try_wait.parity.acquire.cta.shared::cta.b64 p, [%1], 0;\n\t"
            "selp.b32 %0, 1, 0, p;\n\t}"
            : "=r"(done) : "r"(mbar) : "memory");
        while (!done) {
            asm volatile(
                "{\n\t.reg .pred p;\n\t"
                "mbarrier.try_wait.parity.acquire.cta.shared::cta.b64 p, [%1], 0, 0x989680;\n\t"
                "selp.b32 %0, 1, 0, p;\n\t}"
                : "=r"(done) : "r"(mbar) : "memory");
        }
    }

    // ---- FK tree (smem rows -> smem output tile) ----------------------------
    const float* r = s_row + tid * ROWF;
    float* o = s_out + tid * 66;
#define EMIT(j, p) { o[3*(j)] = (p)[0]; o[3*(j)+1] = (p)[1]; o[3*(j)+2] = (p)[2]; }

    const float* R = G;
    float pos0[3] = {G[9], G[10], G[11]};
    EMIT(0, pos0);
    float pos1[3]; fk_pos(pos1, pos0, R, s_off, 1);  EMIT(1, pos1);

    // chain 1 -> 4 -> 7 -> 10
    float R4[9];  fk_rot(R4, R, r, 4);
    float pos4[3];  fk_pos(pos4, pos1, R, s_off, 4);   EMIT(4, pos4);
    float R7[9];  fk_rot(R7, R4, r, 7);
    float pos7[3];  fk_pos(pos7, pos4, R4, s_off, 7);  EMIT(7, pos7);
    float pos10[3]; fk_pos(pos10, pos7, R7, s_off, 10); EMIT(10, pos10);

    // chain 0 -> 2 -> 5 -> 8 -> 11
    float R2[9];  fk_rot(R2, R, r, 2);
    float pos2[3];  fk_pos(pos2, pos0, R, s_off, 2);   EMIT(2, pos2);
    float R5[9];  fk_rot(R5, R2, r, 5);
    float pos5[3];  fk_pos(pos5, pos2, R2, s_off, 5);  EMIT(5, pos5);
    float R8[9];  fk_rot(R8, R5, r, 8);
    float pos8[3];  fk_pos(pos8, pos5, R5, s_off, 8);  EMIT(8, pos8);
    float pos11[3]; fk_pos(pos11, pos8, R8, s_off, 11); EMIT(11, pos11);

    // chain 0 -> 3 -> 6 -> 9
    float R3[9];  fk_rot(R3, R, r, 3);
    float pos3[3];  fk_pos(pos3, pos0, R, s_off, 3);   EMIT(3, pos3);
    float R6[9];  fk_rot(R6, R3, r, 6);
    float pos6[3];  fk_pos(pos6, pos3, R3, s_off, 6);  EMIT(6, pos6);
    float R9[9];  fk_rot(R9, R6, r, 9);
    float pos9[3];  fk_pos(pos9, pos6, R6, s_off, 9);  EMIT(9, pos9);

    // 9 -> 12 -> 15
    float R12[9]; fk_rot(R12, R9, r, 12);
    float pos12[3]; fk_pos(pos12, pos9, R9, s_off, 12); EMIT(12, pos12);
    float pos15[3]; fk_pos(pos15, pos12, R12, s_off, 15); EMIT(15, pos15);

    // 9 -> 13 -> 16 -> 18 -> 20
    float R13[9]; fk_rot(R13, R9, r, 13);
    float pos13[3]; fk_pos(pos13, pos9, R9, s_off, 13); EMIT(13, pos13);
    float R16[9]; fk_rot(R16, R13, r, 16);
    float pos16[3]; fk_pos(pos16, pos13, R13, s_off, 16); EMIT(16, pos16);
    float R18[9]; fk_rot(R18, R16, r, 18);
    float pos18[3]; fk_pos(pos18, pos16, R16, s_off, 18); EMIT(18, pos18);
    float pos20[3]; fk_pos(pos20, pos18, R18, s_off, 20); EMIT(20, pos20);

    // 9 -> 14 -> 17 -> 19 -> 21
    float R14[9]; fk_rot(R14, R9, r, 14);
    float pos14[3]; fk_pos(pos14, pos9, R9, s_off, 14); EMIT(14, pos14);
    float R17[9]; fk_rot(R17, R14, r, 17);
    float pos17[3]; fk_pos(pos17, pos14, R14, s_off, 17); EMIT(17, pos17);
    float R19[9]; fk_rot(R19, R17, r, 19);
    float pos19[3]; fk_pos(pos19, pos17, R17, s_off, 19); EMIT(19, pos19);
    float pos21[3]; fk_pos(pos21, pos19, R19, s_off, 21); EMIT(21, pos21);
#undef EMIT

    __syncthreads();

    // ---- bulk store of the 128x66 output tile ------------------------------
    if (tid == 0) {
        uint32_t sout = (uint32_t)__cvta_generic_to_shared(s_out);
        asm volatile("fence.proxy.async.shared::cta;" ::: "memory");
        asm volatile(
            "cp.async.bulk.global.shared::cta.bulk_group [%0], [%1], %2;"
            :: "l"(out + base * 66), "r"(sout),
               "r"((unsigned)(TPB * 66 * 4)) : "memory");
        asm volatile("cp.async.bulk.commit_group;" ::: "memory");
        asm volatile("cp.async.bulk.wait_group 0;" ::: "memory");
    }
    __syncthreads();
}

// ---------------------------------------------------------------------------
extern "C" void kernel_launch(void* const* d_in, const int* in_sizes, int n_in,
                              void* d_out, int out_size) {
    const float* pred = (const float*)d_in[0];   // (65536, 22, 6) f32
    const float* offs = (const float*)d_in[1];   // (22, 3) f32
    float* out = (float*)d_out;                  // (65536, 22, 3) f32

    cudaFuncSetAttribute(kernelC, cudaFuncAttributeMaxDynamicSharedMemorySize,
                         SMEM_C);
    kernelA<<<NB, TPB>>>(pred);
    kernelB<<<1, NB>>>();
    kernelC<<<NB, TPB, SMEM_C>>>(pred, offs, out);
}

// round 7
// speedup vs baseline: 1.3873x; 1.1478x over previous
#include <cuda_runtime.h>
#include <cstdint>

// ---------------------------------------------------------------------------
// TrajectoryFK, 3-kernel parallel pipeline (R7):
//   A: serial-4 per thread + warp scan; ONE WARP -> one 128-step aggregate
//   B: single-block scan of 512 aggregates -> g_pref (exclusive)
//   C: TMA row staging + in-block rescan + FK (outputs in regs) +
//      smem reuse for output tile + TMA bulk store.  3 blocks/SM.
//
// affine element e_t = (M_t, u_t): M_t = rotmat(joint1 6d), u_t = M_t @ vel_t
// combine(a earlier, b later) = (a.M @ b.M, a.u + a.M @ b.u)
// ---------------------------------------------------------------------------

constexpr int L    = 65536;
constexpr int TPB  = 128;        // timesteps per C block
constexpr int NB   = L / TPB;    // 512 aggregates / C blocks
constexpr int ROWF = 132;        // floats per timestep row (22*6)

// kernel C shared layout (float indices)
constexpr int S_ROW  = 0;                     // 128*132 staged rows (reused as out tile)
constexpr int S_WAGG = TPB * ROWF;            // 16896: 4 warp aggs * 12
constexpr int S_OFF  = S_WAGG + 48;           // 16944: 66 offsets
constexpr int S_MBAR = S_OFF + 66;            // 17010 (even -> 8B aligned)
constexpr int SMEM_C = (S_MBAR + 2) * 4;      // 68,048 B -> 3 blocks/SM

__device__ float g_agg[NB * 12];    // block aggregates
__device__ float g_pref[NB * 12];   // exclusive block prefixes

// ---------------------------------------------------------------------------
__device__ __forceinline__ void d6_to_mat(const float* d, float* m) {
    float a1x = d[0], a1y = d[1], a1z = d[2];
    float a2x = d[3], a2y = d[4], a2z = d[5];
    float n1 = a1x * a1x + a1y * a1y + a1z * a1z;
    float i1 = rsqrtf(fmaxf(n1, 1e-24f));
    float b1x = a1x * i1, b1y = a1y * i1, b1z = a1z * i1;
    float dp = b1x * a2x + b1y * a2y + b1z * a2z;
    float c2x = a2x - b1x * dp, c2y = a2y - b1y * dp, c2z = a2z - b1z * dp;
    float n2 = c2x * c2x + c2y * c2y + c2z * c2z;
    float i2 = rsqrtf(fmaxf(n2, 1e-24f));
    float b2x = c2x * i2, b2y = c2y * i2, b2z = c2z * i2;
    float b3x = b1y * b2z - b1z * b2y;
    float b3y = b1z * b2x - b1x * b2z;
    float b3z = b1x * b2y - b1y * b2x;
    m[0] = b1x; m[1] = b2x; m[2] = b3x;
    m[3] = b1y; m[4] = b2y; m[5] = b3y;
    m[6] = b1z; m[7] = b2z; m[8] = b3z;
}

__device__ __forceinline__ void mat3mul(float* __restrict__ c,
                                        const float* a, const float* b) {
#pragma unroll
    for (int r = 0; r < 3; r++) {
        float a0 = a[r * 3], a1 = a[r * 3 + 1], a2 = a[r * 3 + 2];
#pragma unroll
        for (int k = 0; k < 3; k++)
            c[r * 3 + k] = a0 * b[k] + a1 * b[3 + k] + a2 * b[6 + k];
    }
}

// r = a ∘ b (a earlier); alias-safe
__device__ __forceinline__ void aff_combine(float* r, const float* a, const float* b) {
    float t[12];
#pragma unroll
    for (int rr = 0; rr < 3; rr++) {
        float a0 = a[rr * 3], a1 = a[rr * 3 + 1], a2 = a[rr * 3 + 2];
#pragma unroll
        for (int k = 0; k < 3; k++)
            t[rr * 3 + k] = a0 * b[k] + a1 * b[3 + k] + a2 * b[6 + k];
        t[9 + rr] = a[9 + rr] + a0 * b[9] + a1 * b[10] + a2 * b[11];
    }
#pragma unroll
    for (int i = 0; i < 12; i++) r[i] = t[i];
}

__device__ __forceinline__ void aff_identity(float* v) {
#pragma unroll
    for (int i = 0; i < 12; i++) v[i] = 0.0f;
    v[0] = v[4] = v[8] = 1.0f;
}

// build element from 3 preloaded float4s (row floats 0..11)
__device__ __forceinline__ void build_from_q(float4 q0, float4 q1, float4 q2,
                                             float* val) {
    float d6[6] = {q1.z, q1.w, q2.x, q2.y, q2.z, q2.w};   // floats 6..11
    d6_to_mat(d6, val);
    float vx = q0.x, vy = q0.y, vz = q0.z;                // floats 0..2
    val[9]  = val[0] * vx + val[1] * vy + val[2] * vz;
    val[10] = val[3] * vx + val[4] * vy + val[5] * vz;
    val[11] = val[6] * vx + val[7] * vy + val[8] * vz;
}

// warp-ordered inclusive scan of affine elements
__device__ __forceinline__ void warp_incl_scan(float* val, int lane) {
#pragma unroll
    for (int off = 1; off < 32; off <<= 1) {
        float o[12];
#pragma unroll
        for (int i = 0; i < 12; i++)
            o[i] = __shfl_up_sync(0xffffffffu, val[i], off);
        if (lane >= off) aff_combine(val, o, val);
    }
}

// ---------------------------------------------------------------------------
// Kernel A: one warp per 128-step aggregate. Each thread folds 4 consecutive
// steps serially (ordered), warp scan covers 128, lane 31 = aggregate.
// ---------------------------------------------------------------------------
constexpr int A_TPB   = 256;            // 8 warps
constexpr int A_GRID  = NB / 8;         // 64 blocks

__global__ void __launch_bounds__(A_TPB)
kernelA(const float* __restrict__ pred) {
    const int lane = threadIdx.x & 31;
    const int warp = threadIdx.x >> 5;
    const int wg   = blockIdx.x * 8 + warp;       // 0..511 (aggregate id)
    const size_t t0 = (size_t)wg * TPB + lane * 4;

    // preload 12 float4s (4 rows x floats 0..11) for MLP
    float4 q[12];
#pragma unroll
    for (int k = 0; k < 4; k++) {
        const float4* r4 = (const float4*)(pred + (t0 + k) * ROWF);
        q[3 * k]     = __ldg(r4);
        q[3 * k + 1] = __ldg(r4 + 1);
        q[3 * k + 2] = __ldg(r4 + 2);
    }

    float val[12];
    build_from_q(q[0], q[1], q[2], val);
#pragma unroll
    for (int k = 1; k < 4; k++) {
        float e[12];
        build_from_q(q[3 * k], q[3 * k + 1], q[3 * k + 2], e);
        aff_combine(val, val, e);
    }

    warp_incl_scan(val, lane);

    if (lane == 31) {
#pragma unroll
        for (int i = 0; i < 12; i++) g_agg[wg * 12 + i] = val[i];
    }
}

// ---------------------------------------------------------------------------
// Kernel B: scan 512 block aggregates -> exclusive prefixes.
// ---------------------------------------------------------------------------
__global__ void __launch_bounds__(NB)
kernelB() {
    const int tid = threadIdx.x, lane = tid & 31, warp = tid >> 5;
    float val[12];
#pragma unroll
    for (int i = 0; i < 12; i++) val[i] = g_agg[tid * 12 + i];

    warp_incl_scan(val, lane);

    __shared__ float s_wagg[16][12];
    __shared__ float s_wpre[16][12];
    if (lane == 31) {
#pragma unroll
        for (int i = 0; i < 12; i++) s_wagg[warp][i] = val[i];
    }
    __syncthreads();

    if (warp == 0 && lane < 16) {
        float w[12];
#pragma unroll
        for (int i = 0; i < 12; i++) w[i] = s_wagg[lane][i];
#pragma unroll
        for (int off = 1; off < 16; off <<= 1) {
            float o[12];
#pragma unroll
            for (int i = 0; i < 12; i++)
                o[i] = __shfl_up_sync(0x0000ffffu, w[i], off);
            if (lane >= off) aff_combine(w, o, w);
        }
        float ex[12];
#pragma unroll
        for (int i = 0; i < 12; i++)
            ex[i] = __shfl_up_sync(0x0000ffffu, w[i], 1);
        if (lane == 0) aff_identity(ex);
#pragma unroll
        for (int i = 0; i < 12; i++) s_wpre[lane][i] = ex[i];
    }
    __syncthreads();

    float inc[12];
    aff_combine(inc, s_wpre[warp], val);

    if (tid == 0) {
        float id[12];
        aff_identity(id);
#pragma unroll
        for (int i = 0; i < 12; i++) g_pref[i] = id[i];
    }
    if (tid < NB - 1) {
#pragma unroll
        for (int i = 0; i < 12; i++) g_pref[(tid + 1) * 12 + i] = inc[i];
    }
}

// ---------------------------------------------------------------------------
// Kernel C
// ---------------------------------------------------------------------------
__device__ __forceinline__ void fk_rot(float* Rc, const float* Rp,
                                       const float* r, int j) {
    float d6[6];
#pragma unroll
    for (int i = 0; i < 6; i++) d6[i] = r[6 * j + i];
    float M[9];
    d6_to_mat(d6, M);
    mat3mul(Rc, Rp, M);
}

__device__ __forceinline__ void fk_pos(float* pc, const float* pp, const float* Rp,
                                       const float* s_off, int j) {
    float ox = s_off[j * 3], oy = s_off[j * 3 + 1], oz = s_off[j * 3 + 2];
    pc[0] = pp[0] + Rp[0] * ox + Rp[1] * oy + Rp[2] * oz;
    pc[1] = pp[1] + Rp[3] * ox + Rp[4] * oy + Rp[5] * oz;
    pc[2] = pp[2] + Rp[6] * ox + Rp[7] * oy + Rp[8] * oz;
}

extern "C" __global__ void __launch_bounds__(TPB)
kernelC(const float* __restrict__ pred, const float* __restrict__ offs,
        float* __restrict__ out) {
    extern __shared__ float smem[];
    float* s_row  = smem + S_ROW;
    float* s_wagg = smem + S_WAGG;
    float* s_off  = smem + S_OFF;

    const int tid  = threadIdx.x;
    const int lane = tid & 31;
    const int warp = tid >> 5;
    const int b    = blockIdx.x;
    const size_t base = (size_t)b * TPB;

    uint32_t mbar = (uint32_t)__cvta_generic_to_shared(smem + S_MBAR);
    uint32_t srow = (uint32_t)__cvta_generic_to_shared(s_row);

    // ---- issue TMA bulk load of this block's 128 rows ----------------------
    if (tid == 0) {
        asm volatile("mbarrier.init.shared.b64 [%0], 1;" :: "r"(mbar) : "memory");
        asm volatile("fence.proxy.async.shared::cta;" ::: "memory");
        asm volatile("mbarrier.arrive.expect_tx.shared.b64 _, [%0], %1;"
                     :: "r"(mbar), "r"((unsigned)(TPB * ROWF * 4)) : "memory");
        asm volatile(
            "cp.async.bulk.shared::cluster.global.mbarrier::complete_tx::bytes "
            "[%0], [%1], %2, [%3];"
            :: "r"(srow), "l"(pred + base * ROWF),
               "r"((unsigned)(TPB * ROWF * 4)), "r"(mbar) : "memory");
    }
    if (tid < 66) s_off[tid] = offs[tid];

    // ---- build element from gmem (overlaps TMA; sectors L2-hot) ------------
    float val[12];
    {
        const float4* r4 = (const float4*)(pred + (base + tid) * ROWF);
        float4 q0 = __ldg(r4), q1 = __ldg(r4 + 1), q2 = __ldg(r4 + 2);
        build_from_q(q0, q1, q2, val);
    }
    warp_incl_scan(val, lane);

    if (lane == 31) {
#pragma unroll
        for (int i = 0; i < 12; i++) s_wagg[warp * 12 + i] = val[i];
    }
    __syncthreads();

    float pre[12];
    aff_identity(pre);
    for (int w = 0; w < warp; w++) aff_combine(pre, pre, s_wagg + w * 12);
    float linc[12];
    aff_combine(linc, pre, val);

    float P[12];
#pragma unroll
    for (int i = 0; i < 12; i++) P[i] = __ldg(&g_pref[b * 12 + i]);
    float G[12];
    aff_combine(G, P, linc);

    // ---- wait for TMA row staging ------------------------------------------
    {
        unsigned done;
        asm volatile(
            "{\n\t.reg .pred p;\n\t"
            "mbarrier.try_wait.parity.acquire.cta.shared::cta.b64 p, [%1], 0;\n\t"
            "selp.b32 %0, 1, 0, p;\n\t}"
            : "=r"(done) : "r"(mbar) : "memory");
        while (!done) {
            asm volatile(
                "{\n\t.reg .pred p;\n\t"
                "mbarrier.try_wait.parity.acquire.cta.shared::cta.b64 p, [%1], 0, 0x989680;\n\t"
                "selp.b32 %0, 1, 0, p;\n\t}"
                : "=r"(done) : "r"(mbar) : "memory");
        }
    }

    // ---- FK tree: read smem rows, accumulate 66 outputs in REGISTERS -------
    const float* r = s_row + tid * ROWF;
    float po[66];
#define EMIT(j, p) { po[3*(j)] = (p)[0]; po[3*(j)+1] = (p)[1]; po[3*(j)+2] = (p)[2]; }

    const float* R = G;
    float pos0[3] = {G[9], G[10], G[11]};
    EMIT(0, pos0);
    float pos1[3]; fk_pos(pos1, pos0, R, s_off, 1);  EMIT(1, pos1);

    // chain 1 -> 4 -> 7 -> 10
    float R4[9];  fk_rot(R4, R, r, 4);
    float pos4[3];  fk_pos(pos4, pos1, R, s_off, 4);   EMIT(4, pos4);
    float R7[9];  fk_rot(R7, R4, r, 7);
    float pos7[3];  fk_pos(pos7, pos4, R4, s_off, 7);  EMIT(7, pos7);
    float pos10[3]; fk_pos(pos10, pos7, R7, s_off, 10); EMIT(10, pos10);

    // chain 0 -> 2 -> 5 -> 8 -> 11
    float R2[9];  fk_rot(R2, R, r, 2);
    float pos2[3];  fk_pos(pos2, pos0, R, s_off, 2);   EMIT(2, pos2);
    float R5[9];  fk_rot(R5, R2, r, 5);
    float pos5[3];  fk_pos(pos5, pos2, R2, s_off, 5);  EMIT(5, pos5);
    float R8[9];  fk_rot(R8, R5, r, 8);
    float pos8[3];  fk_pos(pos8, pos5, R5, s_off, 8);  EMIT(8, pos8);
    float pos11[3]; fk_pos(pos11, pos8, R8, s_off, 11); EMIT(11, pos11);

    // chain 0 -> 3 -> 6 -> 9
    float R3[9];  fk_rot(R3, R, r, 3);
    float pos3[3];  fk_pos(pos3, pos0, R, s_off, 3);   EMIT(3, pos3);
    float R6[9];  fk_rot(R6, R3, r, 6);
    float pos6[3];  fk_pos(pos6, pos3, R3, s_off, 6);  EMIT(6, pos6);
    float R9[9];  fk_rot(R9, R6, r, 9);
    float pos9[3];  fk_pos(pos9, pos6, R6, s_off, 9);  EMIT(9, pos9);

    // 9 -> 12 -> 15
    float R12[9]; fk_rot(R12, R9, r, 12);
    float pos12[3]; fk_pos(pos12, pos9, R9, s_off, 12); EMIT(12, pos12);
    float pos15[3]; fk_pos(pos15, pos12, R12, s_off, 15); EMIT(15, pos15);

    // 9 -> 13 -> 16 -> 18 -> 20
    float R13[9]; fk_rot(R13, R9, r, 13);
    float pos13[3]; fk_pos(pos13, pos9, R9, s_off, 13); EMIT(13, pos13);
    float R16[9]; fk_rot(R16, R13, r, 16);
    float pos16[3]; fk_pos(pos16, pos13, R13, s_off, 16); EMIT(16, pos16);
    float R18[9]; fk_rot(R18, R16, r, 18);
    float pos18[3]; fk_pos(pos18, pos16, R16, s_off, 18); EMIT(18, pos18);
    float pos20[3]; fk_pos(pos20, pos18, R18, s_off, 20); EMIT(20, pos20);

    // 9 -> 14 -> 17 -> 19 -> 21
    float R14[9]; fk_rot(R14, R9, r, 14);
    float pos14[3]; fk_pos(pos14, pos9, R9, s_off, 14); EMIT(14, pos14);
    float R17[9]; fk_rot(R17, R14, r, 17);
    float pos17[3]; fk_pos(pos17, pos14, R14, s_off, 17); EMIT(17, pos17);
    float R19[9]; fk_rot(R19, R17, r, 19);
    float pos19[3]; fk_pos(pos19, pos17, R17, s_off, 19); EMIT(19, pos19);
    float pos21[3]; fk_pos(pos21, pos19, R19, s_off, 21); EMIT(21, pos21);
#undef EMIT

    // ---- all row reads done: reuse s_row region as the output tile ---------
    __syncthreads();
    float* s_out = s_row;                 // 128*66 floats, contiguous
    {
        float2* o2 = (float2*)(s_out + tid * 66);
#pragma unroll
        for (int i = 0; i < 33; i++)
            o2[i] = make_float2(po[2 * i], po[2 * i + 1]);
    }
    __syncthreads();

    if (tid == 0) {
        uint32_t sout = (uint32_t)__cvta_generic_to_shared(s_out);
        asm volatile("fence.proxy.async.shared::cta;" ::: "memory");
        asm volatile(
            "cp.async.bulk.global.shared::cta.bulk_group [%0], [%1], %2;"
            :: "l"(out + base * 66), "r"(sout),
               "r"((unsigned)(TPB * 66 * 4)) : "memory");
        asm volatile("cp.async.bulk.commit_group;" ::: "memory");
        asm volatile("cp.async.bulk.wait_group 0;" ::: "memory");
    }
    __syncthreads();
}

// ---------------------------------------------------------------------------
extern "C" void kernel_launch(void* const* d_in, const int* in_sizes, int n_in,
                              void* d_out, int out_size) {
    const float* pred = (const float*)d_in[0];   // (65536, 22, 6) f32
    const float* offs = (const float*)d_in[1];   // (22, 3) f32
    float* out = (float*)d_out;                  // (65536, 22, 3) f32

    cudaFuncSetAttribute(kernelC, cudaFuncAttributeMaxDynamicSharedMemorySize,
                         SMEM_C);
    kernelA<<<A_GRID, A_TPB>>>(pred);
    kernelB<<<1, NB>>>();
    kernelC<<<NB, TPB, SMEM_C>>>(pred, offs, out);
}

// round 12
// speedup vs baseline: 1.3908x; 1.0026x over previous
#include <cuda_runtime.h>
#include <cstdint>

// ---------------------------------------------------------------------------
// TrajectoryFK, 3-kernel parallel pipeline (R11 = R10 + mbarrier race fix):
//   A: TMA-staged 128-row tile -> build elems from smem -> warp scan -> agg
//   B: single-block scan of 512 aggregates -> g_pref (exclusive)
//   C: TMA row staging + in-block rescan + FK (outputs in regs) +
//      smem reuse for output tile + TMA bulk store.  3 blocks/SM.
//
// mbarrier protocol (both A and C): tid0 init -> __syncthreads -> tid0 issues
// TMA -> (overlapped work) -> all wait.  R10 crashed because threads could
// try_wait an uninitialized mbarrier.
// ---------------------------------------------------------------------------

constexpr int L    = 65536;
constexpr int TPB  = 128;        // timesteps per block (A and C)
constexpr int NB   = L / TPB;    // 512 aggregates / blocks
constexpr int ROWF = 132;        // floats per timestep row (22*6)

// kernel A shared layout (float indices)
constexpr int SA_ROW  = 0;                    // 128*132 staged rows
constexpr int SA_WAGG = TPB * ROWF;           // 16896: 4 warp aggs * 12
constexpr int SA_MBAR = SA_WAGG + 48;         // 16944 (even -> 8B aligned)
constexpr int SMEM_A  = (SA_MBAR + 2) * 4;    // 67,784 B -> 3 blocks/SM

// kernel C shared layout (float indices)
constexpr int S_ROW  = 0;                     // 128*132 staged rows (reused as out tile)
constexpr int S_WAGG = TPB * ROWF;            // 16896: 4 warp aggs * 12
constexpr int S_OFF  = S_WAGG + 48;           // 16944: 66 offsets
constexpr int S_MBAR = S_OFF + 66;            // 17010 (even -> 8B aligned)
constexpr int SMEM_C = (S_MBAR + 2) * 4;      // 68,048 B -> 3 blocks/SM

__device__ float g_agg[NB * 12];    // block aggregates
__device__ float g_pref[NB * 12];   // exclusive block prefixes

// ---------------------------------------------------------------------------
__device__ __forceinline__ void d6_to_mat(const float* d, float* m) {
    float a1x = d[0], a1y = d[1], a1z = d[2];
    float a2x = d[3], a2y = d[4], a2z = d[5];
    float n1 = a1x * a1x + a1y * a1y + a1z * a1z;
    float i1 = rsqrtf(fmaxf(n1, 1e-24f));
    float b1x = a1x * i1, b1y = a1y * i1, b1z = a1z * i1;
    float dp = b1x * a2x + b1y * a2y + b1z * a2z;
    float c2x = a2x - b1x * dp, c2y = a2y - b1y * dp, c2z = a2z - b1z * dp;
    float n2 = c2x * c2x + c2y * c2y + c2z * c2z;
    float i2 = rsqrtf(fmaxf(n2, 1e-24f));
    float b2x = c2x * i2, b2y = c2y * i2, b2z = c2z * i2;
    float b3x = b1y * b2z - b1z * b2y;
    float b3y = b1z * b2x - b1x * b2z;
    float b3z = b1x * b2y - b1y * b2x;
    m[0] = b1x; m[1] = b2x; m[2] = b3x;
    m[3] = b1y; m[4] = b2y; m[5] = b3y;
    m[6] = b1z; m[7] = b2z; m[8] = b3z;
}

__device__ __forceinline__ void mat3mul(float* __restrict__ c,
                                        const float* a, const float* b) {
#pragma unroll
    for (int r = 0; r < 3; r++) {
        float a0 = a[r * 3], a1 = a[r * 3 + 1], a2 = a[r * 3 + 2];
#pragma unroll
        for (int k = 0; k < 3; k++)
            c[r * 3 + k] = a0 * b[k] + a1 * b[3 + k] + a2 * b[6 + k];
    }
}

// r = a ∘ b (a earlier); alias-safe
__device__ __forceinline__ void aff_combine(float* r, const float* a, const float* b) {
    float t[12];
#pragma unroll
    for (int rr = 0; rr < 3; rr++) {
        float a0 = a[rr * 3], a1 = a[rr * 3 + 1], a2 = a[rr * 3 + 2];
#pragma unroll
        for (int k = 0; k < 3; k++)
            t[rr * 3 + k] = a0 * b[k] + a1 * b[3 + k] + a2 * b[6 + k];
        t[9 + rr] = a[9 + rr] + a0 * b[9] + a1 * b[10] + a2 * b[11];
    }
#pragma unroll
    for (int i = 0; i < 12; i++) r[i] = t[i];
}

__device__ __forceinline__ void aff_identity(float* v) {
#pragma unroll
    for (int i = 0; i < 12; i++) v[i] = 0.0f;
    v[0] = v[4] = v[8] = 1.0f;
}

// build element from 12 leading floats of a row
__device__ __forceinline__ void build_from12(const float* q, float* val) {
    float d6[6] = {q[6], q[7], q[8], q[9], q[10], q[11]};
    d6_to_mat(d6, val);
    float vx = q[0], vy = q[1], vz = q[2];
    val[9]  = val[0] * vx + val[1] * vy + val[2] * vz;
    val[10] = val[3] * vx + val[4] * vy + val[5] * vz;
    val[11] = val[6] * vx + val[7] * vy + val[8] * vz;
}

// warp-ordered inclusive scan of affine elements
__device__ __forceinline__ void warp_incl_scan(float* val, int lane) {
#pragma unroll
    for (int off = 1; off < 32; off <<= 1) {
        float o[12];
#pragma unroll
        for (int i = 0; i < 12; i++)
            o[i] = __shfl_up_sync(0xffffffffu, val[i], off);
        if (lane >= off) aff_combine(val, o, val);
    }
}

// mbarrier wait, phase 0
__device__ __forceinline__ void mbar_wait0(uint32_t mbar) {
    unsigned done;
    asm volatile(
        "{\n\t.reg .pred p;\n\t"
        "mbarrier.try_wait.parity.acquire.cta.shared::cta.b64 p, [%1], 0;\n\t"
        "selp.b32 %0, 1, 0, p;\n\t}"
        : "=r"(done) : "r"(mbar) : "memory");
    while (!done) {
        asm volatile(
            "{\n\t.reg .pred p;\n\t"
            "mbarrier.try_wait.parity.acquire.cta.shared::cta.b64 p, [%1], 0, 0x989680;\n\t"
            "selp.b32 %0, 1, 0, p;\n\t}"
            : "=r"(done) : "r"(mbar) : "memory");
    }
}

__device__ __forceinline__ void mbar_init1(uint32_t mbar) {
    asm volatile("mbarrier.init.shared.b64 [%0], 1;" :: "r"(mbar) : "memory");
    asm volatile("fence.proxy.async.shared::cta;" ::: "memory");
}

// issue bulk TMA load of one 128-row tile into smem (mbar already inited)
__device__ __forceinline__ void tile_load_issue(uint32_t dst, const float* src,
                                                uint32_t mbar) {
    asm volatile("mbarrier.arrive.expect_tx.shared.b64 _, [%0], %1;"
                 :: "r"(mbar), "r"((unsigned)(TPB * ROWF * 4)) : "memory");
    asm volatile(
        "cp.async.bulk.shared::cluster.global.mbarrier::complete_tx::bytes "
        "[%0], [%1], %2, [%3];"
        :: "r"(dst), "l"(src), "r"((unsigned)(TPB * ROWF * 4)), "r"(mbar)
        : "memory");
}

// ---------------------------------------------------------------------------
// Kernel A: TMA-staged tile -> elems from smem -> warp scan -> block aggregate.
// ---------------------------------------------------------------------------
__global__ void __launch_bounds__(TPB)
kernelA(const float* __restrict__ pred) {
    extern __shared__ float smem[];
    float* s_row  = smem + SA_ROW;
    float* s_wagg = smem + SA_WAGG;

    const int tid  = threadIdx.x;
    const int lane = tid & 31;
    const int warp = tid >> 5;
    const int b    = blockIdx.x;

    uint32_t mbar = (uint32_t)__cvta_generic_to_shared(smem + SA_MBAR);
    uint32_t srow = (uint32_t)__cvta_generic_to_shared(s_row);

    if (tid == 0) mbar_init1(mbar);
    __syncthreads();                       // init visible to ALL before any wait
    if (tid == 0)
        tile_load_issue(srow, pred + (size_t)b * TPB * ROWF, mbar);

    mbar_wait0(mbar);

    float val[12];
    build_from12(s_row + tid * ROWF, val);
    warp_incl_scan(val, lane);

    if (lane == 31) {
#pragma unroll
        for (int i = 0; i < 12; i++) s_wagg[warp * 12 + i] = val[i];
    }
    __syncthreads();

    if (tid == 0) {
        float agg[12];
#pragma unroll
        for (int i = 0; i < 12; i++) agg[i] = s_wagg[i];
        aff_combine(agg, agg, s_wagg + 12);
        aff_combine(agg, agg, s_wagg + 24);
        aff_combine(agg, agg, s_wagg + 36);
#pragma unroll
        for (int i = 0; i < 12; i++) g_agg[b * 12 + i] = agg[i];
    }
}

// ---------------------------------------------------------------------------
// Kernel B: scan 512 block aggregates -> exclusive prefixes.
// ---------------------------------------------------------------------------
__global__ void __launch_bounds__(NB)
kernelB() {
    const int tid = threadIdx.x, lane = tid & 31, warp = tid >> 5;
    float val[12];
#pragma unroll
    for (int i = 0; i < 12; i++) val[i] = g_agg[tid * 12 + i];

    warp_incl_scan(val, lane);

    __shared__ float s_wagg[16][12];
    __shared__ float s_wpre[16][12];
    if (lane == 31) {
#pragma unroll
        for (int i = 0; i < 12; i++) s_wagg[warp][i] = val[i];
    }
    __syncthreads();

    if (warp == 0 && lane < 16) {
        float w[12];
#pragma unroll
        for (int i = 0; i < 12; i++) w[i] = s_wagg[lane][i];
#pragma unroll
        for (int off = 1; off < 16; off <<= 1) {
            float o[12];
#pragma unroll
            for (int i = 0; i < 12; i++)
                o[i] = __shfl_up_sync(0x0000ffffu, w[i], off);
            if (lane >= off) aff_combine(w, o, w);
        }
        float ex[12];
#pragma unroll
        for (int i = 0; i < 12; i++)
            ex[i] = __shfl_up_sync(0x0000ffffu, w[i], 1);
        if (lane == 0) aff_identity(ex);
#pragma unroll
        for (int i = 0; i < 12; i++) s_wpre[lane][i] = ex[i];
    }
    __syncthreads();

    float inc[12];
    aff_combine(inc, s_wpre[warp], val);

    if (tid == 0) {
        float id[12];
        aff_identity(id);
#pragma unroll
        for (int i = 0; i < 12; i++) g_pref[i] = id[i];
    }
    if (tid < NB - 1) {
#pragma unroll
        for (int i = 0; i < 12; i++) g_pref[(tid + 1) * 12 + i] = inc[i];
    }
}

// ---------------------------------------------------------------------------
// Kernel C
// ---------------------------------------------------------------------------
__device__ __forceinline__ void fk_rot(float* Rc, const float* Rp,
                                       const float* r, int j) {
    float d6[6];
#pragma unroll
    for (int i = 0; i < 6; i++) d6[i] = r[6 * j + i];
    float M[9];
    d6_to_mat(d6, M);
    mat3mul(Rc, Rp, M);
}

__device__ __forceinline__ void fk_pos(float* pc, const float* pp, const float* Rp,
                                       const float* s_off, int j) {
    float ox = s_off[j * 3], oy = s_off[j * 3 + 1], oz = s_off[j * 3 + 2];
    pc[0] = pp[0] + Rp[0] * ox + Rp[1] * oy + Rp[2] * oz;
    pc[1] = pp[1] + Rp[3] * ox + Rp[4] * oy + Rp[5] * oz;
    pc[2] = pp[2] + Rp[6] * ox + Rp[7] * oy + Rp[8] * oz;
}

extern "C" __global__ void __launch_bounds__(TPB)
kernelC(const float* __restrict__ pred, const float* __restrict__ offs,
        float* __restrict__ out) {
    extern __shared__ float smem[];
    float* s_row  = smem + S_ROW;
    float* s_wagg = smem + S_WAGG;
    float* s_off  = smem + S_OFF;

    const int tid  = threadIdx.x;
    const int lane = tid & 31;
    const int warp = tid >> 5;
    const int b    = blockIdx.x;
    const size_t base = (size_t)b * TPB;

    uint32_t mbar = (uint32_t)__cvta_generic_to_shared(smem + S_MBAR);
    uint32_t srow = (uint32_t)__cvta_generic_to_shared(s_row);

    if (tid == 0) mbar_init1(mbar);
    __syncthreads();                       // init visible before any wait
    if (tid == 0)
        tile_load_issue(srow, pred + base * ROWF, mbar);
    if (tid < 66) s_off[tid] = offs[tid];

    // ---- build element from gmem (overlaps TMA; lines L2-hot from A) -------
    float val[12];
    {
        const float4* r4 = (const float4*)(pred + (base + tid) * ROWF);
        float4 q0 = __ldg(r4), q1 = __ldg(r4 + 1), q2 = __ldg(r4 + 2);
        float q[12] = {q0.x, q0.y, q0.z, q0.w, q1.x, q1.y, q1.z, q1.w,
                       q2.x, q2.y, q2.z, q2.w};
        build_from12(q, val);
    }
    warp_incl_scan(val, lane);

    if (lane == 31) {
#pragma unroll
        for (int i = 0; i < 12; i++) s_wagg[warp * 12 + i] = val[i];
    }
    __syncthreads();

    float pre[12];
    aff_identity(pre);
    for (int w = 0; w < warp; w++) aff_combine(pre, pre, s_wagg + w * 12);
    float linc[12];
    aff_combine(linc, pre, val);

    float P[12];
#pragma unroll
    for (int i = 0; i < 12; i++) P[i] = __ldg(&g_pref[b * 12 + i]);
    float G[12];
    aff_combine(G, P, linc);

    // ---- wait for TMA row staging ------------------------------------------
    mbar_wait0(mbar);

    // ---- FK tree: read smem rows, accumulate 66 outputs in REGISTERS -------
    const float* r = s_row + tid * ROWF;
    float po[66];
#define EMIT(j, p) { po[3*(j)] = (p)[0]; po[3*(j)+1] = (p)[1]; po[3*(j)+2] = (p)[2]; }

    const float* R = G;
    float pos0[3] = {G[9], G[10], G[11]};
    EMIT(0, pos0);
    float pos1[3]; fk_pos(pos1, pos0, R, s_off, 1);  EMIT(1, pos1);

    // chain 1 -> 4 -> 7 -> 10
    float R4[9];  fk_rot(R4, R, r, 4);
    float pos4[3];  fk_pos(pos4, pos1, R, s_off, 4);   EMIT(4, pos4);
    float R7[9];  fk_rot(R7, R4, r, 7);
    float pos7[3];  fk_pos(pos7, pos4, R4, s_off, 7);  EMIT(7, pos7);
    float pos10[3]; fk_pos(pos10, pos7, R7, s_off, 10); EMIT(10, pos10);

    // chain 0 -> 2 -> 5 -> 8 -> 11
    float R2[9];  fk_rot(R2, R, r, 2);
    float pos2[3];  fk_pos(pos2, pos0, R, s_off, 2);   EMIT(2, pos2);
    float R5[9];  fk_rot(R5, R2, r, 5);
    float pos5[3];  fk_pos(pos5, pos2, R2, s_off, 5);  EMIT(5, pos5);
    float R8[9];  fk_rot(R8, R5, r, 8);
    float pos8[3];  fk_pos(pos8, pos5, R5, s_off, 8);  EMIT(8, pos8);
    float pos11[3]; fk_pos(pos11, pos8, R8, s_off, 11); EMIT(11, pos11);

    // chain 0 -> 3 -> 6 -> 9
    float R3[9];  fk_rot(R3, R, r, 3);
    float pos3[3];  fk_pos(pos3, pos0, R, s_off, 3);   EMIT(3, pos3);
    float R6[9];  fk_rot(R6, R3, r, 6);
    float pos6[3];  fk_pos(pos6, pos3, R3, s_off, 6);  EMIT(6, pos6);
    float R9[9];  fk_rot(R9, R6, r, 9);
    float pos9[3];  fk_pos(pos9, pos6, R6, s_off, 9);  EMIT(9, pos9);

    // 9 -> 12 -> 15
    float R12[9]; fk_rot(R12, R9, r, 12);
    float pos12[3]; fk_pos(pos12, pos9, R9, s_off, 12); EMIT(12, pos12);
    float pos15[3]; fk_pos(pos15, pos12, R12, s_off, 15); EMIT(15, pos15);

    // 9 -> 13 -> 16 -> 18 -> 20
    float R13[9]; fk_rot(R13, R9, r, 13);
    float pos13[3]; fk_pos(pos13, pos9, R9, s_off, 13); EMIT(13, pos13);
    float R16[9]; fk_rot(R16, R13, r, 16);
    float pos16[3]; fk_pos(pos16, pos13, R13, s_off, 16); EMIT(16, pos16);
    float R18[9]; fk_rot(R18, R16, r, 18);
    float pos18[3]; fk_pos(pos18, pos16, R16, s_off, 18); EMIT(18, pos18);
    float pos20[3]; fk_pos(pos20, pos18, R18, s_off, 20); EMIT(20, pos20);

    // 9 -> 14 -> 17 -> 19 -> 21
    float R14[9]; fk_rot(R14, R9, r, 14);
    float pos14[3]; fk_pos(pos14, pos9, R9, s_off, 14); EMIT(14, pos14);
    float R17[9]; fk_rot(R17, R14, r, 17);
    float pos17[3]; fk_pos(pos17, pos14, R14, s_off, 17); EMIT(17, pos17);
    float R19[9]; fk_rot(R19, R17, r, 19);
    float pos19[3]; fk_pos(pos19, pos17, R17, s_off, 19); EMIT(19, pos19);
    float pos21[3]; fk_pos(pos21, pos19, R19, s_off, 21); EMIT(21, pos21);
#undef EMIT

    // ---- all row reads done: reuse s_row region as the output tile ---------
    __syncthreads();
    float* s_out = s_row;                 // 128*66 floats, contiguous
    {
        float2* o2 = (float2*)(s_out + tid * 66);
#pragma unroll
        for (int i = 0; i < 33; i++)
            o2[i] = make_float2(po[2 * i], po[2 * i + 1]);
    }
    __syncthreads();

    if (tid == 0) {
        uint32_t sout = (uint32_t)__cvta_generic_to_shared(s_out);
        asm volatile("fence.proxy.async.shared::cta;" ::: "memory");
        asm volatile(
            "cp.async.bulk.global.shared::cta.bulk_group [%0], [%1], %2;"
            :: "l"(out + base * 66), "r"(sout),
               "r"((unsigned)(TPB * 66 * 4)) : "memory");
        asm volatile("cp.async.bulk.commit_group;" ::: "memory");
        asm volatile("cp.async.bulk.wait_group 0;" ::: "memory");
    }
    __syncthreads();
}

// ---------------------------------------------------------------------------
extern "C" void kernel_launch(void* const* d_in, const int* in_sizes, int n_in,
                              void* d_out, int out_size) {
    const float* pred = (const float*)d_in[0];   // (65536, 22, 6) f32
    const float* offs = (const float*)d_in[1];   // (22, 3) f32
    float* out = (float*)d_out;                  // (65536, 22, 3) f32

    cudaFuncSetAttribute(kernelA, cudaFuncAttributeMaxDynamicSharedMemorySize,
                         SMEM_A);
    cudaFuncSetAttribute(kernelC, cudaFuncAttributeMaxDynamicSharedMemorySize,
                         SMEM_C);
    kernelA<<<NB, TPB, SMEM_A>>>(pred);
    kernelB<<<1, NB>>>();
    kernelC<<<NB, TPB, SMEM_C>>>(pred, offs, out);
}

// round 15
// speedup vs baseline: 1.4161x; 1.0182x over previous
#include <cuda_runtime.h>
#include <cstdint>

// ---------------------------------------------------------------------------
// TrajectoryFK R13: 2-kernel pipeline.
//   AB: strided-LDG aggregate build (only 48B/row touched) spread over 128
//       SMs + explicit L2 prefetch of full rows for C + fused tail-scan (B)
//       via fence/atomic counter (graph-replay safe: counter self-resets).
//   C:  TMA row staging + in-block rescan + FK (outputs in regs) +
//       smem reuse for output tile + TMA bulk store.  3 blocks/SM.
//
// affine element e_t = (M_t, u_t): M_t = rotmat(joint1 6d), u_t = M_t @ vel_t
// combine(a earlier, b later) = (a.M @ b.M, a.u + a.M @ b.u)
// ---------------------------------------------------------------------------

constexpr int L    = 65536;
constexpr int TPB  = 128;        // timesteps per C block / per aggregate
constexpr int NB   = L / TPB;    // 512 aggregates / C blocks
constexpr int ROWF = 132;        // floats per timestep row (22*6)

// kernel AB config: 128 blocks x 256 threads; block covers 4 aggregates
constexpr int AB_TPB   = 256;
constexpr int AB_GRID  = NB / 4;           // 128
constexpr int AB_ROWS  = 4 * TPB;          // 512 rows per block
constexpr unsigned AB_BYTES = AB_ROWS * ROWF * 4;  // 270,336 B

// kernel C shared layout (float indices)
constexpr int S_ROW  = 0;                     // 128*132 staged rows (reused as out tile)
constexpr int S_WAGG = TPB * ROWF;            // 16896: 4 warp aggs * 12
constexpr int S_OFF  = S_WAGG + 48;           // 16944: 66 offsets
constexpr int S_MBAR = S_OFF + 66;            // 17010 (even -> 8B aligned)
constexpr int SMEM_C = (S_MBAR + 2) * 4;      // 68,048 B -> 3 blocks/SM

__device__ float    g_agg[NB * 12];    // block aggregates
__device__ float    g_pref[NB * 12];   // exclusive block prefixes
__device__ unsigned g_cnt = 0;         // arrival counter (self-resetting)

// ---------------------------------------------------------------------------
__device__ __forceinline__ void d6_to_mat(const float* d, float* m) {
    float a1x = d[0], a1y = d[1], a1z = d[2];
    float a2x = d[3], a2y = d[4], a2z = d[5];
    float n1 = a1x * a1x + a1y * a1y + a1z * a1z;
    float i1 = rsqrtf(fmaxf(n1, 1e-24f));
    float b1x = a1x * i1, b1y = a1y * i1, b1z = a1z * i1;
    float dp = b1x * a2x + b1y * a2y + b1z * a2z;
    float c2x = a2x - b1x * dp, c2y = a2y - b1y * dp, c2z = a2z - b1z * dp;
    float n2 = c2x * c2x + c2y * c2y + c2z * c2z;
    float i2 = rsqrtf(fmaxf(n2, 1e-24f));
    float b2x = c2x * i2, b2y = c2y * i2, b2z = c2z * i2;
    float b3x = b1y * b2z - b1z * b2y;
    float b3y = b1z * b2x - b1x * b2z;
    float b3z = b1x * b2y - b1y * b2x;
    m[0] = b1x; m[1] = b2x; m[2] = b3x;
    m[3] = b1y; m[4] = b2y; m[5] = b3y;
    m[6] = b1z; m[7] = b2z; m[8] = b3z;
}

__device__ __forceinline__ void mat3mul(float* __restrict__ c,
                                        const float* a, const float* b) {
#pragma unroll
    for (int r = 0; r < 3; r++) {
        float a0 = a[r * 3], a1 = a[r * 3 + 1], a2 = a[r * 3 + 2];
#pragma unroll
        for (int k = 0; k < 3; k++)
            c[r * 3 + k] = a0 * b[k] + a1 * b[3 + k] + a2 * b[6 + k];
    }
}

// r = a ∘ b (a earlier); alias-safe
__device__ __forceinline__ void aff_combine(float* r, const float* a, const float* b) {
    float t[12];
#pragma unroll
    for (int rr = 0; rr < 3; rr++) {
        float a0 = a[rr * 3], a1 = a[rr * 3 + 1], a2 = a[rr * 3 + 2];
#pragma unroll
        for (int k = 0; k < 3; k++)
            t[rr * 3 + k] = a0 * b[k] + a1 * b[3 + k] + a2 * b[6 + k];
        t[9 + rr] = a[9 + rr] + a0 * b[9] + a1 * b[10] + a2 * b[11];
    }
#pragma unroll
    for (int i = 0; i < 12; i++) r[i] = t[i];
}

__device__ __forceinline__ void aff_identity(float* v) {
#pragma unroll
    for (int i = 0; i < 12; i++) v[i] = 0.0f;
    v[0] = v[4] = v[8] = 1.0f;
}

// build element from 12 leading floats of a row
__device__ __forceinline__ void build_from12(const float* q, float* val) {
    float d6[6] = {q[6], q[7], q[8], q[9], q[10], q[11]};
    d6_to_mat(d6, val);
    float vx = q[0], vy = q[1], vz = q[2];
    val[9]  = val[0] * vx + val[1] * vy + val[2] * vz;
    val[10] = val[3] * vx + val[4] * vy + val[5] * vz;
    val[11] = val[6] * vx + val[7] * vy + val[8] * vz;
}

// warp-ordered inclusive scan of affine elements
__device__ __forceinline__ void warp_incl_scan(float* val, int lane) {
#pragma unroll
    for (int off = 1; off < 32; off <<= 1) {
        float o[12];
#pragma unroll
        for (int i = 0; i < 12; i++)
            o[i] = __shfl_up_sync(0xffffffffu, val[i], off);
        if (lane >= off) aff_combine(val, o, val);
    }
}

// mbarrier wait, phase 0
__device__ __forceinline__ void mbar_wait0(uint32_t mbar) {
    unsigned done;
    asm volatile(
        "{\n\t.reg .pred p;\n\t"
        "mbarrier.try_wait.parity.acquire.cta.shared::cta.b64 p, [%1], 0;\n\t"
        "selp.b32 %0, 1, 0, p;\n\t}"
        : "=r"(done) : "r"(mbar) : "memory");
    while (!done) {
        asm volatile(
            "{\n\t.reg .pred p;\n\t"
            "mbarrier.try_wait.parity.acquire.cta.shared::cta.b64 p, [%1], 0, 0x989680;\n\t"
            "selp.b32 %0, 1, 0, p;\n\t}"
            : "=r"(done) : "r"(mbar) : "memory");
    }
}

__device__ __forceinline__ void mbar_init1(uint32_t mbar) {
    asm volatile("mbarrier.init.shared.b64 [%0], 1;" :: "r"(mbar) : "memory");
    asm volatile("fence.proxy.async.shared::cta;" ::: "memory");
}

// issue bulk TMA load of one 128-row tile into smem (mbar already inited)
__device__ __forceinline__ void tile_load_issue(uint32_t dst, const float* src,
                                                uint32_t mbar) {
    asm volatile("mbarrier.arrive.expect_tx.shared.b64 _, [%0], %1;"
                 :: "r"(mbar), "r"((unsigned)(TPB * ROWF * 4)) : "memory");
    asm volatile(
        "cp.async.bulk.shared::cluster.global.mbarrier::complete_tx::bytes "
        "[%0], [%1], %2, [%3];"
        :: "r"(dst), "l"(src), "r"((unsigned)(TPB * ROWF * 4)), "r"(mbar)
        : "memory");
}

// ---------------------------------------------------------------------------
// Kernel AB: aggregates + L2 prefetch + fused tail scan-of-aggregates.
//   block b covers rows [512b, 512b+512) = aggregates [4b, 4b+4).
//   warp w (0..7): pair p = w>>1 -> aggregate 4b+p; half h = w&1.
//   thread: rows r0 = 512b + p*128 + h*64 + lane*2, r0+1 (serial combine).
// ---------------------------------------------------------------------------
__global__ void __launch_bounds__(AB_TPB)
kernelAB(const float* __restrict__ pred) {
    __shared__ float s_wagg[8][12];
    __shared__ unsigned s_tail;

    const int tid  = threadIdx.x;
    const int lane = tid & 31;
    const int warp = tid >> 5;
    const int b    = blockIdx.x;
    const size_t rowbase = (size_t)b * AB_ROWS;

    // L2 prefetch of this block's FULL rows for kernel C (fire-and-forget)
    if (tid == 0) {
        const char* src = (const char*)(pred + rowbase * ROWF);
#pragma unroll
        for (int k = 0; k < 4; k++) {
            asm volatile("cp.async.bulk.prefetch.L2.global [%0], %1;"
                         :: "l"(src + (size_t)k * (AB_BYTES / 4)),
                            "r"(AB_BYTES / 4) : "memory");
        }
    }

    // strided loads: only floats 0..11 of each row (3 x float4, 2 rows)
    const size_t r0 = rowbase + (size_t)(warp >> 1) * 128 + (warp & 1) * 64
                    + lane * 2;
    const float4* p0 = (const float4*)(pred + r0 * ROWF);
    const float4* p1 = (const float4*)(pred + (r0 + 1) * ROWF);
    float4 a0 = __ldg(p0), a1 = __ldg(p0 + 1), a2 = __ldg(p0 + 2);
    float4 b0 = __ldg(p1), b1 = __ldg(p1 + 1), b2 = __ldg(p1 + 2);

    float val[12], e[12];
    {
        float qa[12] = {a0.x, a0.y, a0.z, a0.w, a1.x, a1.y, a1.z, a1.w,
                        a2.x, a2.y, a2.z, a2.w};
        build_from12(qa, val);
        float qb[12] = {b0.x, b0.y, b0.z, b0.w, b1.x, b1.y, b1.z, b1.w,
                        b2.x, b2.y, b2.z, b2.w};
        build_from12(qb, e);
        aff_combine(val, val, e);
    }
    warp_incl_scan(val, lane);

    if (lane == 31) {
#pragma unroll
        for (int i = 0; i < 12; i++) s_wagg[warp][i] = val[i];
    }
    __syncthreads();

    // aggregate 4b+t = halfA ∘ halfB  (t = 0..3)
    if (tid < 4) {
        float agg[12];
#pragma unroll
        for (int i = 0; i < 12; i++) agg[i] = s_wagg[2 * tid][i];
        aff_combine(agg, agg, s_wagg[2 * tid + 1]);
#pragma unroll
        for (int i = 0; i < 12; i++) g_agg[(4 * b + tid) * 12 + i] = agg[i];
    }
    __syncthreads();

    // arrival counter; last block performs the aggregate scan (old kernel B)
    if (tid == 0) {
        __threadfence();
        unsigned old = atomicAdd(&g_cnt, 1u);
        s_tail = (old == AB_GRID - 1) ? 1u : 0u;
    }
    __syncthreads();
    if (s_tail == 0) return;

    // ---- tail block: scan 512 aggregates -> exclusive prefixes -------------
    __threadfence();   // acquire side: make all g_agg writes visible

    // thread t handles aggregates 2t, 2t+1
    float pa[12], pb[12];
#pragma unroll
    for (int i = 0; i < 12; i++) pa[i] = g_agg[(2 * tid) * 12 + i];
#pragma unroll
    for (int i = 0; i < 12; i++) pb[i] = g_agg[(2 * tid + 1) * 12 + i];

    float inc[12];
#pragma unroll
    for (int i = 0; i < 12; i++) inc[i] = pa[i];
    aff_combine(inc, inc, pb);
    warp_incl_scan(inc, lane);           // inclusive over pairs within warp

    __shared__ float s_b[8][12];
    __shared__ float s_bp[8][12];
    if (lane == 31) {
#pragma unroll
        for (int i = 0; i < 12; i++) s_b[warp][i] = inc[i];
    }
    __syncthreads();
    if (warp == 0 && lane < 8) {
        float w[12];
#pragma unroll
        for (int i = 0; i < 12; i++) w[i] = s_b[lane][i];
#pragma unroll
        for (int off = 1; off < 8; off <<= 1) {
            float o[12];
#pragma unroll
            for (int i = 0; i < 12; i++)
                o[i] = __shfl_up_sync(0x000000ffu, w[i], off);
            if (lane >= off) aff_combine(w, o, w);
        }
        float ex[12];
#pragma unroll
        for (int i = 0; i < 12; i++)
            ex[i] = __shfl_up_sync(0x000000ffu, w[i], 1);
        if (lane == 0) aff_identity(ex);
#pragma unroll
        for (int i = 0; i < 12; i++) s_bp[lane][i] = ex[i];
    }
    __syncthreads();

    // exclusive prefix before pair t: W_warp ∘ (incl of pairs < t in warp)
    float et[12];
#pragma unroll
    for (int i = 0; i < 12; i++)
        et[i] = __shfl_up_sync(0xffffffffu, inc[i], 1);
    float excl[12];
#pragma unroll
    for (int i = 0; i < 12; i++) excl[i] = s_bp[warp][i];
    if (lane > 0) aff_combine(excl, excl, et);

    // g_pref[2t] = excl ; g_pref[2t+1] = excl ∘ a(2t)
#pragma unroll
    for (int i = 0; i < 12; i++) g_pref[(2 * tid) * 12 + i] = excl[i];
    aff_combine(excl, excl, pa);
#pragma unroll
    for (int i = 0; i < 12; i++) g_pref[(2 * tid + 1) * 12 + i] = excl[i];

    __syncthreads();
    if (tid == 0) g_cnt = 0;             // reset for next graph replay
}

// ---------------------------------------------------------------------------
// Kernel C (unchanged from R12, which passed)
// ---------------------------------------------------------------------------
__device__ __forceinline__ void fk_rot(float* Rc, const float* Rp,
                                       const float* r, int j) {
    float d6[6];
#pragma unroll
    for (int i = 0; i < 6; i++) d6[i] = r[6 * j + i];
    float M[9];
    d6_to_mat(d6, M);
    mat3mul(Rc, Rp, M);
}

__device__ __forceinline__ void fk_pos(float* pc, const float* pp, const float* Rp,
                                       const float* s_off, int j) {
    float ox = s_off[j * 3], oy = s_off[j * 3 + 1], oz = s_off[j * 3 + 2];
    pc[0] = pp[0] + Rp[0] * ox + Rp[1] * oy + Rp[2] * oz;
    pc[1] = pp[1] + Rp[3] * ox + Rp[4] * oy + Rp[5] * oz;
    pc[2] = pp[2] + Rp[6] * ox + Rp[7] * oy + Rp[8] * oz;
}

extern "C" __global__ void __launch_bounds__(TPB)
kernelC(const float* __restrict__ pred, const float* __restrict__ offs,
        float* __restrict__ out) {
    extern __shared__ float smem[];
    float* s_row  = smem + S_ROW;
    float* s_wagg = smem + S_WAGG;
    float* s_off  = smem + S_OFF;

    const int tid  = threadIdx.x;
    const int lane = tid & 31;
    const int warp = tid >> 5;
    const int b    = blockIdx.x;
    const size_t base = (size_t)b * TPB;

    uint32_t mbar = (uint32_t)__cvta_generic_to_shared(smem + S_MBAR);
    uint32_t srow = (uint32_t)__cvta_generic_to_shared(s_row);

    if (tid == 0) mbar_init1(mbar);
    __syncthreads();                       // init visible before any wait
    if (tid == 0)
        tile_load_issue(srow, pred + base * ROWF, mbar);
    if (tid < 66) s_off[tid] = offs[tid];

    // ---- build element from gmem (overlaps TMA; lines L2-hot) --------------
    float val[12];
    {
        const float4* r4 = (const float4*)(pred + (base + tid) * ROWF);
        float4 q0 = __ldg(r4), q1 = __ldg(r4 + 1), q2 = __ldg(r4 + 2);
        float q[12] = {q0.x, q0.y, q0.z, q0.w, q1.x, q1.y, q1.z, q1.w,
                       q2.x, q2.y, q2.z, q2.w};
        build_from12(q, val);
    }
    warp_incl_scan(val, lane);

    if (lane == 31) {
#pragma unroll
        for (int i = 0; i < 12; i++) s_wagg[warp * 12 + i] = val[i];
    }
    __syncthreads();

    float pre[12];
    aff_identity(pre);
    for (int w = 0; w < warp; w++) aff_combine(pre, pre, s_wagg + w * 12);
    float linc[12];
    aff_combine(linc, pre, val);

    float P[12];
#pragma unroll
    for (int i = 0; i < 12; i++) P[i] = __ldg(&g_pref[b * 12 + i]);
    float G[12];
    aff_combine(G, P, linc);

    // ---- wait for TMA row staging ------------------------------------------
    mbar_wait0(mbar);

    // ---- FK tree: read smem rows, accumulate 66 outputs in REGISTERS -------
    const float* r = s_row + tid * ROWF;
    float po[66];
#define EMIT(j, p) { po[3*(j)] = (p)[0]; po[3*(j)+1] = (p)[1]; po[3*(j)+2] = (p)[2]; }

    const float* R = G;
    float pos0[3] = {G[9], G[10], G[11]};
    EMIT(0, pos0);
    float pos1[3]; fk_pos(pos1, pos0, R, s_off, 1);  EMIT(1, pos1);

    // chain 1 -> 4 -> 7 -> 10
    float R4[9];  fk_rot(R4, R, r, 4);
    float pos4[3];  fk_pos(pos4, pos1, R, s_off, 4);   EMIT(4, pos4);
    float R7[9];  fk_rot(R7, R4, r, 7);
    float pos7[3];  fk_pos(pos7, pos4, R4, s_off, 7);  EMIT(7, pos7);
    float pos10[3]; fk_pos(pos10, pos7, R7, s_off, 10); EMIT(10, pos10);

    // chain 0 -> 2 -> 5 -> 8 -> 11
    float R2[9];  fk_rot(R2, R, r, 2);
    float pos2[3];  fk_pos(pos2, pos0, R, s_off, 2);   EMIT(2, pos2);
    float R5[9];  fk_rot(R5, R2, r, 5);
    float pos5[3];  fk_pos(pos5, pos2, R2, s_off, 5);  EMIT(5, pos5);
    float R8[9];  fk_rot(R8, R5, r, 8);
    float pos8[3];  fk_pos(pos8, pos5, R5, s_off, 8);  EMIT(8, pos8);
    float pos11[3]; fk_pos(pos11, pos8, R8, s_off, 11); EMIT(11, pos11);

    // chain 0 -> 3 -> 6 -> 9
    float R3[9];  fk_rot(R3, R, r, 3);
    float pos3[3];  fk_pos(pos3, pos0, R, s_off, 3);   EMIT(3, pos3);
    float R6[9];  fk_rot(R6, R3, r, 6);
    float pos6[3];  fk_pos(pos6, pos3, R3, s_off, 6);  EMIT(6, pos6);
    float R9[9];  fk_rot(R9, R6, r, 9);
    float pos9[3];  fk_pos(pos9, pos6, R6, s_off, 9);  EMIT(9, pos9);

    // 9 -> 12 -> 15
    float R12[9]; fk_rot(R12, R9, r, 12);
    float pos12[3]; fk_pos(pos12, pos9, R9, s_off, 12); EMIT(12, pos12);
    float pos15[3]; fk_pos(pos15, pos12, R12, s_off, 15); EMIT(15, pos15);

    // 9 -> 13 -> 16 -> 18 -> 20
    float R13[9]; fk_rot(R13, R9, r, 13);
    float pos13[3]; fk_pos(pos13, pos9, R9, s_off, 13); EMIT(13, pos13);
    float R16[9]; fk_rot(R16, R13, r, 16);
    float pos16[3]; fk_pos(pos16, pos13, R13, s_off, 16); EMIT(16, pos16);
    float R18[9]; fk_rot(R18, R16, r, 18);
    float pos18[3]; fk_pos(pos18, pos16, R16, s_off, 18); EMIT(18, pos18);
    float pos20[3]; fk_pos(pos20, pos18, R18, s_off, 20); EMIT(20, pos20);

    // 9 -> 14 -> 17 -> 19 -> 21
    float R14[9]; fk_rot(R14, R9, r, 14);
    float pos14[3]; fk_pos(pos14, pos9, R9, s_off, 14); EMIT(14, pos14);
    float R17[9]; fk_rot(R17, R14, r, 17);
    float pos17[3]; fk_pos(pos17, pos14, R14, s_off, 17); EMIT(17, pos17);
    float R19[9]; fk_rot(R19, R17, r, 19);
    float pos19[3]; fk_pos(pos19, pos17, R17, s_off, 19); EMIT(19, pos19);
    float pos21[3]; fk_pos(pos21, pos19, R19, s_off, 21); EMIT(21, pos21);
#undef EMIT

    // ---- all row reads done: reuse s_row region as the output tile ---------
    __syncthreads();
    float* s_out = s_row;                 // 128*66 floats, contiguous
    {
        float2* o2 = (float2*)(s_out + tid * 66);
#pragma unroll
        for (int i = 0; i < 33; i++)
            o2[i] = make_float2(po[2 * i], po[2 * i + 1]);
    }
    __syncthreads();

    if (tid == 0) {
        uint32_t sout = (uint32_t)__cvta_generic_to_shared(s_out);
        asm volatile("fence.proxy.async.shared::cta;" ::: "memory");
        asm volatile(
            "cp.async.bulk.global.shared::cta.bulk_group [%0], [%1], %2;"
            :: "l"(out + base * 66), "r"(sout),
               "r"((unsigned)(TPB * 66 * 4)) : "memory");
        asm volatile("cp.async.bulk.commit_group;" ::: "memory");
        asm volatile("cp.async.bulk.wait_group 0;" ::: "memory");
    }
    __syncthreads();
}

// ---------------------------------------------------------------------------
extern "C" void kernel_launch(void* const* d_in, const int* in_sizes, int n_in,
                              void* d_out, int out_size) {
    const float* pred = (const float*)d_in[0];   // (65536, 22, 6) f32
    const float* offs = (const float*)d_in[1];   // (22, 3) f32
    float* out = (float*)d_out;                  // (65536, 22, 3) f32

    cudaFuncSetAttribute(kernelC, cudaFuncAttributeMaxDynamicSharedMemorySize,
                         SMEM_C);
    kernelAB<<<AB_GRID, AB_TPB>>>(pred);
    kernelC<<<NB, TPB, SMEM_C>>>(pred, offs, out);
}